// round 1
// baseline (speedup 1.0000x reference)
#include <cuda_runtime.h>
#include <cstdint>

// EnsembleRBF: out[m,n,d] = sum_c exp(-||x_n - c_c||^2) * sigma^2 * W[m,c,d]
// N=100000, C=256, D=2, M=5, sigma=0.25
//
// Strategy: FMA-pipe-bound kernel using Blackwell packed f32x2 FMA (PTX-only),
// exp folded into a single ex2.approx, centers+weights broadcast from smem.

#define C_CENTERS 256
#define M_MODELS 5

__device__ __forceinline__ uint64_t pack2(float lo, float hi) {
    uint64_t r;
    asm("mov.b64 %0, {%1, %2};" : "=l"(r) : "f"(lo), "f"(hi));
    return r;
}
__device__ __forceinline__ void unpack2(uint64_t v, float& lo, float& hi) {
    asm("mov.b64 {%0, %1}, %2;" : "=f"(lo), "=f"(hi) : "l"(v));
}
__device__ __forceinline__ uint64_t add2(uint64_t a, uint64_t b) {
    uint64_t d;
    asm("add.rn.f32x2 %0, %1, %2;" : "=l"(d) : "l"(a), "l"(b));
    return d;
}
__device__ __forceinline__ uint64_t mul2(uint64_t a, uint64_t b) {
    uint64_t d;
    asm("mul.rn.f32x2 %0, %1, %2;" : "=l"(d) : "l"(a), "l"(b));
    return d;
}
__device__ __forceinline__ uint64_t fma2(uint64_t a, uint64_t b, uint64_t c) {
    uint64_t d;
    asm("fma.rn.f32x2 %0, %1, %2, %3;" : "=l"(d) : "l"(a), "l"(b), "l"(c));
    return d;
}
__device__ __forceinline__ float ex2_approx(float x) {
    float r;
    asm("ex2.approx.ftz.f32 %0, %1;" : "=f"(r) : "f"(x));
    return r;
}

__global__ void __launch_bounds__(256, 4)
ensemble_rbf_kernel(const float* __restrict__ x,
                    const float* __restrict__ centers,
                    const float* __restrict__ weights,
                    float* __restrict__ out,
                    int n) {
    // smem: negated centers (so distance is add2) + weights re-laid-out [c][m]
    __shared__ float2 negc[C_CENTERS];
    __shared__ float2 wsm[C_CENTERS * M_MODELS];

    const int tid = threadIdx.x;

    // Stage centers: [C, 2] -> negated float2
    {
        float2 c = reinterpret_cast<const float2*>(centers)[tid];
        negc[tid] = make_float2(-c.x, -c.y);
    }
    // Stage weights: [M, C, 2] -> wsm[c*M + m]
#pragma unroll
    for (int m = 0; m < M_MODELS; m++) {
        float2 w = reinterpret_cast<const float2*>(weights)[m * C_CENTERS + tid];
        wsm[tid * M_MODELS + m] = w;
    }
    __syncthreads();

    const int i = blockIdx.x * 256 + tid;
    float2 xi = make_float2(0.0f, 0.0f);
    if (i < n) xi = reinterpret_cast<const float2*>(x)[i];
    const uint64_t xp = pack2(xi.x, xi.y);

    uint64_t acc0 = pack2(0.0f, 0.0f);
    uint64_t acc1 = acc0, acc2 = acc0, acc3 = acc0, acc4 = acc0;

    // exp(-d2) * 0.0625 = exp2(-log2(e) * d2 - 4)
    const float NL2E = -1.4426950408889634f;

#pragma unroll 8
    for (int c = 0; c < C_CENTERS; c++) {
        float2 nc = negc[c];
        uint64_t diff = add2(xp, pack2(nc.x, nc.y));
        uint64_t sq = mul2(diff, diff);
        float sx, sy;
        unpack2(sq, sx, sy);
        float t = fmaf(sx, NL2E, fmaf(sy, NL2E, -4.0f));
        float r = ex2_approx(t);
        uint64_t r2 = pack2(r, r);

        float2 w0 = wsm[c * M_MODELS + 0];
        float2 w1 = wsm[c * M_MODELS + 1];
        float2 w2 = wsm[c * M_MODELS + 2];
        float2 w3 = wsm[c * M_MODELS + 3];
        float2 w4 = wsm[c * M_MODELS + 4];
        acc0 = fma2(r2, pack2(w0.x, w0.y), acc0);
        acc1 = fma2(r2, pack2(w1.x, w1.y), acc1);
        acc2 = fma2(r2, pack2(w2.x, w2.y), acc2);
        acc3 = fma2(r2, pack2(w3.x, w3.y), acc3);
        acc4 = fma2(r2, pack2(w4.x, w4.y), acc4);
    }

    if (i < n) {
        float lo, hi;
        float2* o = reinterpret_cast<float2*>(out);
        unpack2(acc0, lo, hi); o[0 * n + i] = make_float2(lo, hi);
        unpack2(acc1, lo, hi); o[1 * n + i] = make_float2(lo, hi);
        unpack2(acc2, lo, hi); o[2 * n + i] = make_float2(lo, hi);
        unpack2(acc3, lo, hi); o[3 * n + i] = make_float2(lo, hi);
        unpack2(acc4, lo, hi); o[4 * n + i] = make_float2(lo, hi);
    }
}

extern "C" void kernel_launch(void* const* d_in, const int* in_sizes, int n_in,
                              void* d_out, int out_size) {
    const float* x = (const float*)d_in[0];        // [N, 2]
    const float* centers = (const float*)d_in[1];  // [256, 2]
    const float* weights = (const float*)d_in[2];  // [5, 256, 2]
    float* out = (float*)d_out;                    // [5, N, 2]

    const int n = in_sizes[0] / 2;
    const int blocks = (n + 255) / 256;
    ensemble_rbf_kernel<<<blocks, 256>>>(x, centers, weights, out, n);
}

// round 2
// speedup vs baseline: 1.2092x; 1.2092x over previous
#include <cuda_runtime.h>
#include <cstdint>

// EnsembleRBF: out[m,n,d] = sum_c exp(-||x_n - c_c||^2) * sigma^2 * W[m,c,d]
// N=100000, C=256, D=2, M=5, sigma=0.25
//
// R2: expanded-distance formulation (s factor hoisted out of the C loop),
// float4 smem broadcasts (4 LDS / 2 points), P=2 points per thread.

#define C_CENTERS 256
#define M_MODELS 5
#define TPB 128
#define PTS_PER_BLOCK (TPB * 2)

__device__ __forceinline__ uint64_t pack2(float lo, float hi) {
    uint64_t r;
    asm("mov.b64 %0, {%1, %2};" : "=l"(r) : "f"(lo), "f"(hi));
    return r;
}
__device__ __forceinline__ void unpack2(uint64_t v, float& lo, float& hi) {
    asm("mov.b64 {%0, %1}, %2;" : "=f"(lo), "=f"(hi) : "l"(v));
}
__device__ __forceinline__ uint64_t fma2(uint64_t a, uint64_t b, uint64_t c) {
    uint64_t d;
    asm("fma.rn.f32x2 %0, %1, %2, %3;" : "=l"(d) : "l"(a), "l"(b), "l"(c));
    return d;
}
__device__ __forceinline__ uint64_t mul2(uint64_t a, uint64_t b) {
    uint64_t d;
    asm("mul.rn.f32x2 %0, %1, %2;" : "=l"(d) : "l"(a), "l"(b));
    return d;
}
__device__ __forceinline__ float ex2_approx(float x) {
    float r;
    asm("ex2.approx.ftz.f32 %0, %1;" : "=f"(r) : "f"(x));
    return r;
}

__global__ void __launch_bounds__(TPB)
ensemble_rbf_kernel(const float* __restrict__ x,
                    const float* __restrict__ centers,
                    const float* __restrict__ weights,
                    float* __restrict__ out,
                    int n) {
    // Smem, all broadcast-read in the main loop:
    //   g4[c]  = (2*L2E*cx, 2*L2E*cy, -L2E*(cx^2+cy^2), 0)
    //   w01[c] = (w0x, w0y, w1x, w1y)
    //   w23[c] = (w2x, w2y, w3x, w3y)
    //   w4s[c] = (w4x, w4y)
    __shared__ float4 g4[C_CENTERS];
    __shared__ float4 w01[C_CENTERS];
    __shared__ float4 w23[C_CENTERS];
    __shared__ float2 w4s[C_CENTERS];

    const int tid = threadIdx.x;
    const float L2E = 1.4426950408889634f;

    const float2* centers2 = reinterpret_cast<const float2*>(centers);
    const float2* weights2 = reinterpret_cast<const float2*>(weights);

#pragma unroll
    for (int c = tid; c < C_CENTERS; c += TPB) {
        float2 cc = centers2[c];
        float c2 = cc.x * cc.x + cc.y * cc.y;
        g4[c] = make_float4(2.0f * L2E * cc.x, 2.0f * L2E * cc.y, -L2E * c2, 0.0f);
        float2 a0 = weights2[0 * C_CENTERS + c];
        float2 a1 = weights2[1 * C_CENTERS + c];
        float2 a2 = weights2[2 * C_CENTERS + c];
        float2 a3 = weights2[3 * C_CENTERS + c];
        float2 a4 = weights2[4 * C_CENTERS + c];
        w01[c] = make_float4(a0.x, a0.y, a1.x, a1.y);
        w23[c] = make_float4(a2.x, a2.y, a3.x, a3.y);
        w4s[c] = a4;
    }
    __syncthreads();

    // Each thread handles points i0, i0+1 (n is even -> both valid together).
    const int pairIdx = blockIdx.x * TPB + tid;
    const int i0 = pairIdx * 2;
    if (i0 >= n) return;

    const float4 xp = reinterpret_cast<const float4*>(x)[pairIdx];
    const float xx0 = xp.x, xy0 = xp.y, xx1 = xp.z, xy1 = xp.w;

    // per-point hoisted scale: s = exp2(-L2E*||x||^2 - 4)  (sigma^2 folded in)
    const float x2_0 = fmaf(xx0, xx0, xy0 * xy0);
    const float x2_1 = fmaf(xx1, xx1, xy1 * xy1);
    const float s0 = ex2_approx(fmaf(x2_0, -L2E, -4.0f));
    const float s1 = ex2_approx(fmaf(x2_1, -L2E, -4.0f));

    uint64_t z = pack2(0.0f, 0.0f);
    uint64_t a00 = z, a01 = z, a02 = z, a03 = z, a04 = z;  // point 0, models 0..4
    uint64_t a10 = z, a11 = z, a12 = z, a13 = z, a14 = z;  // point 1

#pragma unroll 8
    for (int c = 0; c < C_CENTERS; c++) {
        float4 g = g4[c];
        float t0 = fmaf(xx0, g.x, fmaf(xy0, g.y, g.z));
        float t1 = fmaf(xx1, g.x, fmaf(xy1, g.y, g.z));
        float r0 = ex2_approx(t0);
        float r1 = ex2_approx(t1);
        uint64_t r0p = pack2(r0, r0);
        uint64_t r1p = pack2(r1, r1);

        float4 wa = w01[c];
        float4 wb = w23[c];
        float2 wc = w4s[c];
        uint64_t w0p = pack2(wa.x, wa.y);
        uint64_t w1p = pack2(wa.z, wa.w);
        uint64_t w2p = pack2(wb.x, wb.y);
        uint64_t w3p = pack2(wb.z, wb.w);
        uint64_t w4p = pack2(wc.x, wc.y);

        a00 = fma2(r0p, w0p, a00);
        a10 = fma2(r1p, w0p, a10);
        a01 = fma2(r0p, w1p, a01);
        a11 = fma2(r1p, w1p, a11);
        a02 = fma2(r0p, w2p, a02);
        a12 = fma2(r1p, w2p, a12);
        a03 = fma2(r0p, w3p, a03);
        a13 = fma2(r1p, w3p, a13);
        a04 = fma2(r0p, w4p, a04);
        a14 = fma2(r1p, w4p, a14);
    }

    const uint64_t s0p = pack2(s0, s0);
    const uint64_t s1p = pack2(s1, s1);

    // out layout: [M, N, 2]; points i0, i0+1 contiguous -> one float4 store per model
    float lo0, hi0, lo1, hi1;
    float* ob = out;
#pragma unroll
    for (int m = 0; m < M_MODELS; m++) {
        uint64_t p0, p1;
        switch (m) {
            case 0: p0 = a00; p1 = a10; break;
            case 1: p0 = a01; p1 = a11; break;
            case 2: p0 = a02; p1 = a12; break;
            case 3: p0 = a03; p1 = a13; break;
            default: p0 = a04; p1 = a14; break;
        }
        p0 = mul2(p0, s0p);
        p1 = mul2(p1, s1p);
        unpack2(p0, lo0, hi0);
        unpack2(p1, lo1, hi1);
        float4 v = make_float4(lo0, hi0, lo1, hi1);
        *reinterpret_cast<float4*>(ob + (size_t)m * n * 2 + (size_t)i0 * 2) = v;
    }
}

extern "C" void kernel_launch(void* const* d_in, const int* in_sizes, int n_in,
                              void* d_out, int out_size) {
    const float* x = (const float*)d_in[0];        // [N, 2]
    const float* centers = (const float*)d_in[1];  // [256, 2]
    const float* weights = (const float*)d_in[2];  // [5, 256, 2]
    float* out = (float*)d_out;                    // [5, N, 2]

    const int n = in_sizes[0] / 2;
    const int blocks = (n + PTS_PER_BLOCK - 1) / PTS_PER_BLOCK;
    ensemble_rbf_kernel<<<blocks, TPB>>>(x, centers, weights, out, n);
}

// round 3
// speedup vs baseline: 1.3401x; 1.1083x over previous
#include <cuda_runtime.h>
#include <cstdint>

// EnsembleRBF: out[m,n,d] = sum_c exp(-||x_n - c_c||^2) * sigma^2 * W[m,c,d]
// N=100000, C=256, D=2, M=5, sigma=0.25
//
// R3: C-split across block halves (2x warp parallelism), fully packed f32x2
// score computation, smem reduction.

#define C_CENTERS 256
#define M_MODELS 5
#define TPB 256
#define PAIRS_PER_BLOCK 128
#define PTS_PER_BLOCK (PAIRS_PER_BLOCK * 2)

__device__ __forceinline__ uint64_t pack2(float lo, float hi) {
    uint64_t r;
    asm("mov.b64 %0, {%1, %2};" : "=l"(r) : "f"(lo), "f"(hi));
    return r;
}
__device__ __forceinline__ void unpack2(uint64_t v, float& lo, float& hi) {
    asm("mov.b64 {%0, %1}, %2;" : "=f"(lo), "=f"(hi) : "l"(v));
}
__device__ __forceinline__ uint64_t fma2(uint64_t a, uint64_t b, uint64_t c) {
    uint64_t d;
    asm("fma.rn.f32x2 %0, %1, %2, %3;" : "=l"(d) : "l"(a), "l"(b), "l"(c));
    return d;
}
__device__ __forceinline__ uint64_t add2(uint64_t a, uint64_t b) {
    uint64_t d;
    asm("add.rn.f32x2 %0, %1, %2;" : "=l"(d) : "l"(a), "l"(b));
    return d;
}
__device__ __forceinline__ uint64_t mul2(uint64_t a, uint64_t b) {
    uint64_t d;
    asm("mul.rn.f32x2 %0, %1, %2;" : "=l"(d) : "l"(a), "l"(b));
    return d;
}
__device__ __forceinline__ float ex2_approx(float x) {
    float r;
    asm("ex2.approx.ftz.f32 %0, %1;" : "=f"(r) : "f"(x));
    return r;
}

__global__ void __launch_bounds__(TPB)
ensemble_rbf_kernel(const float* __restrict__ x,
                    const float* __restrict__ centers,
                    const float* __restrict__ weights,
                    float* __restrict__ out,
                    int n) {
    // Broadcast tables (warp-uniform reads in the main loop):
    //   gxy[c] = (2*L2E*cx, 2*L2E*cx, 2*L2E*cy, 2*L2E*cy)   (pre-duplicated)
    //   gz[c]  = (-L2E*|c|^2, -L2E*|c|^2)
    //   w01/w23/w4s: weights re-laid-out per-center
    __shared__ float4 gxy[C_CENTERS];
    __shared__ float2 gz[C_CENTERS];
    __shared__ float4 w01[C_CENTERS];
    __shared__ float4 w23[C_CENTERS];
    __shared__ float2 w4s[C_CENTERS];
    // Cross-half reduction buffer: [acc_slot][pair] -> conflict-free
    __shared__ uint64_t redbuf[M_MODELS * 2][PAIRS_PER_BLOCK];

    const int tid = threadIdx.x;
    const int lane = tid & (PAIRS_PER_BLOCK - 1);  // pair index within block
    const int half = tid >> 7;                      // 0 or 1: which C half
    const float L2E = 1.4426950408889634f;

    // Stage tables: one center per thread
    {
        const float2 cc = reinterpret_cast<const float2*>(centers)[tid];
        const float gx = 2.0f * L2E * cc.x;
        const float gy = 2.0f * L2E * cc.y;
        const float gzv = -L2E * (cc.x * cc.x + cc.y * cc.y);
        gxy[tid] = make_float4(gx, gx, gy, gy);
        gz[tid] = make_float2(gzv, gzv);
        const float2* w2 = reinterpret_cast<const float2*>(weights);
        float2 a0 = w2[0 * C_CENTERS + tid];
        float2 a1 = w2[1 * C_CENTERS + tid];
        float2 a2 = w2[2 * C_CENTERS + tid];
        float2 a3 = w2[3 * C_CENTERS + tid];
        float2 a4 = w2[4 * C_CENTERS + tid];
        w01[tid] = make_float4(a0.x, a0.y, a1.x, a1.y);
        w23[tid] = make_float4(a2.x, a2.y, a3.x, a3.y);
        w4s[tid] = a4;
    }
    __syncthreads();

    const int pairIdx = blockIdx.x * PAIRS_PER_BLOCK + lane;
    const bool valid = (pairIdx * 2) < n;

    float4 xp = make_float4(0.0f, 0.0f, 0.0f, 0.0f);
    if (valid) xp = reinterpret_cast<const float4*>(x)[pairIdx];
    const float xx0 = xp.x, xy0 = xp.y, xx1 = xp.z, xy1 = xp.w;
    const uint64_t xxp = pack2(xx0, xx1);
    const uint64_t xyp = pack2(xy0, xy1);

    uint64_t acc[M_MODELS * 2];  // acc[m*2+p]: model m, point p, packed (d0,d1)
#pragma unroll
    for (int k = 0; k < M_MODELS * 2; k++) acc[k] = pack2(0.0f, 0.0f);

    const int cbase = half * (C_CENTERS / 2);

#pragma unroll 8
    for (int k = 0; k < C_CENTERS / 2; k++) {
        const int c = cbase + k;
        const float4 gq = gxy[c];        // (gx,gx,gy,gy)
        const float2 gzp = gz[c];        // (gz,gz)
        // t for both points in one packed chain
        uint64_t t = fma2(xxp, pack2(gq.x, gq.y),
                     fma2(xyp, pack2(gq.z, gq.w), pack2(gzp.x, gzp.y)));
        float t0, t1;
        unpack2(t, t0, t1);
        const float r0 = ex2_approx(t0);
        const float r1 = ex2_approx(t1);
        const uint64_t r0p = pack2(r0, r0);
        const uint64_t r1p = pack2(r1, r1);

        const float4 wa = w01[c];
        const float4 wb = w23[c];
        const float2 wc = w4s[c];
        const uint64_t w0p = pack2(wa.x, wa.y);
        const uint64_t w1p = pack2(wa.z, wa.w);
        const uint64_t w2p = pack2(wb.x, wb.y);
        const uint64_t w3p = pack2(wb.z, wb.w);
        const uint64_t w4p = pack2(wc.x, wc.y);

        acc[0] = fma2(r0p, w0p, acc[0]);
        acc[1] = fma2(r1p, w0p, acc[1]);
        acc[2] = fma2(r0p, w1p, acc[2]);
        acc[3] = fma2(r1p, w1p, acc[3]);
        acc[4] = fma2(r0p, w2p, acc[4]);
        acc[5] = fma2(r1p, w2p, acc[5]);
        acc[6] = fma2(r0p, w3p, acc[6]);
        acc[7] = fma2(r1p, w3p, acc[7]);
        acc[8] = fma2(r0p, w4p, acc[8]);
        acc[9] = fma2(r1p, w4p, acc[9]);
    }

    // Cross-half reduction: half 1 publishes, half 0 combines + stores.
    if (half == 1) {
#pragma unroll
        for (int k = 0; k < M_MODELS * 2; k++) redbuf[k][lane] = acc[k];
    }
    __syncthreads();

    if (half == 0 && valid) {
        // hoisted per-point scale: s = exp2(-L2E*|x|^2 - 4)
        const float s0 = ex2_approx(fmaf(fmaf(xx0, xx0, xy0 * xy0), -L2E, -4.0f));
        const float s1 = ex2_approx(fmaf(fmaf(xx1, xx1, xy1 * xy1), -L2E, -4.0f));
        const uint64_t s0p = pack2(s0, s0);
        const uint64_t s1p = pack2(s1, s1);

        const int i0 = pairIdx * 2;
#pragma unroll
        for (int m = 0; m < M_MODELS; m++) {
            uint64_t p0 = add2(acc[m * 2 + 0], redbuf[m * 2 + 0][lane]);
            uint64_t p1 = add2(acc[m * 2 + 1], redbuf[m * 2 + 1][lane]);
            p0 = mul2(p0, s0p);
            p1 = mul2(p1, s1p);
            float lo0, hi0, lo1, hi1;
            unpack2(p0, lo0, hi0);
            unpack2(p1, lo1, hi1);
            *reinterpret_cast<float4*>(out + (size_t)m * n * 2 + (size_t)i0 * 2) =
                make_float4(lo0, hi0, lo1, hi1);
        }
    }
}

extern "C" void kernel_launch(void* const* d_in, const int* in_sizes, int n_in,
                              void* d_out, int out_size) {
    const float* x = (const float*)d_in[0];        // [N, 2]
    const float* centers = (const float*)d_in[1];  // [256, 2]
    const float* weights = (const float*)d_in[2];  // [5, 256, 2]
    float* out = (float*)d_out;                    // [5, N, 2]

    const int n = in_sizes[0] / 2;
    const int blocks = (n + PTS_PER_BLOCK - 1) / PTS_PER_BLOCK;
    ensemble_rbf_kernel<<<blocks, TPB>>>(x, centers, weights, out, n);
}